// round 5
// baseline (speedup 1.0000x reference)
#include <cuda_runtime.h>
#include <cstddef>

typedef unsigned long long u64;

// Problem constants
constexpr int SEQ  = 1024;
constexpr int HID  = 1024;
constexpr int NH   = 16;
constexpr int HD   = 64;
constexpr int BB   = 4;
constexpr int BH   = BB * NH;      // 64

// Scratch (head-major Q/K/V): [bh][s][d]
__device__ float g_Q[(size_t)BH * SEQ * HD];
__device__ float g_K[(size_t)BH * SEQ * HD];
__device__ float g_V[(size_t)BH * SEQ * HD];

// ---------------------------------------------------------------------------
// Packed fp32x2 helpers (sm_103a)
// ---------------------------------------------------------------------------
__device__ __forceinline__ u64 ffma2(u64 a, u64 b, u64 c) {
    u64 d;
    asm("fma.rn.f32x2 %0, %1, %2, %3;" : "=l"(d) : "l"(a), "l"(b), "l"(c));
    return d;
}
__device__ __forceinline__ u64 fadd2(u64 a, u64 b) {
    u64 d;
    asm("add.rn.f32x2 %0, %1, %2;" : "=l"(d) : "l"(a), "l"(b));
    return d;
}
__device__ __forceinline__ u64 fmul2(u64 a, u64 b) {
    u64 d;
    asm("mul.rn.f32x2 %0, %1, %2;" : "=l"(d) : "l"(a), "l"(b));
    return d;
}
__device__ __forceinline__ u64 pack2(float lo, float hi) {
    u64 d;
    asm("mov.b64 %0, {%1, %2};" : "=l"(d) : "f"(lo), "f"(hi));
    return d;
}
__device__ __forceinline__ float2 unpack2(u64 v) {
    float lo, hi;
    asm("mov.b64 {%0, %1}, %2;" : "=f"(lo), "=f"(hi) : "l"(v));
    return make_float2(lo, hi);
}

// ---------------------------------------------------------------------------
// Kernel 1: fused QKV projection (unchanged)
// ---------------------------------------------------------------------------
constexpr int BM = 128;
constexpr int BN = 64;
constexpr int BK = 16;

__global__ __launch_bounds__(256)
void qkv_kernel(const float* __restrict__ X, const float* __restrict__ W,
                const float* __restrict__ bias) {
    __shared__ float As[BK][BM + 4];
    __shared__ float Bs[BK][BN + 4];

    const int n0  = blockIdx.x * BN;
    const int m0  = blockIdx.y * BM;
    const int tid = threadIdx.x;
    const int tn  = tid & 15;
    const int tm  = tid >> 4;

    u64 acc2[4][4];
#pragma unroll
    for (int jj = 0; jj < 4; jj++)
#pragma unroll
        for (int ii = 0; ii < 4; ii++) acc2[jj][ii] = 0ull;

    for (int k0 = 0; k0 < HID; k0 += BK) {
#pragma unroll
        for (int p = 0; p < 2; p++) {
            int idx = tid + p * 256;
            int row = idx >> 2, c4 = idx & 3;
            float4 v = *(const float4*)(X + (size_t)(m0 + row) * HID + k0 + c4 * 4);
            As[c4 * 4 + 0][row] = v.x; As[c4 * 4 + 1][row] = v.y;
            As[c4 * 4 + 2][row] = v.z; As[c4 * 4 + 3][row] = v.w;
        }
        {
            int row = tid >> 2, c4 = tid & 3;
            float4 v = *(const float4*)(W + (size_t)(n0 + row) * HID + k0 + c4 * 4);
            Bs[c4 * 4 + 0][row] = v.x; Bs[c4 * 4 + 1][row] = v.y;
            Bs[c4 * 4 + 2][row] = v.z; Bs[c4 * 4 + 3][row] = v.w;
        }
        __syncthreads();
#pragma unroll
        for (int k = 0; k < BK; k++) {
            u64 a2[4];
#pragma unroll
            for (int ii = 0; ii < 4; ii++)
                a2[ii] = *(const u64*)(&As[k][tm * 8 + ii * 2]);
            float4 b4 = *(const float4*)(&Bs[k][tn * 4]);
            u64 bb[4];
            bb[0] = pack2(b4.x, b4.x); bb[1] = pack2(b4.y, b4.y);
            bb[2] = pack2(b4.z, b4.z); bb[3] = pack2(b4.w, b4.w);
#pragma unroll
            for (int jj = 0; jj < 4; jj++)
#pragma unroll
                for (int ii = 0; ii < 4; ii++)
                    acc2[jj][ii] = ffma2(a2[ii], bb[jj], acc2[jj][ii]);
        }
        __syncthreads();
    }

    const int part = n0 >> 10;
    const int head = (n0 & 1023) >> 6;
    float* dst = (part == 0) ? g_Q : (part == 1) ? g_K : g_V;
    float4 b4 = *(const float4*)(bias + n0 + tn * 4);
#pragma unroll
    for (int ii = 0; ii < 4; ii++) {
        float2 c0 = unpack2(acc2[0][ii]);
        float2 c1 = unpack2(acc2[1][ii]);
        float2 c2 = unpack2(acc2[2][ii]);
        float2 c3 = unpack2(acc2[3][ii]);
#pragma unroll
        for (int h = 0; h < 2; h++) {
            int i = ii * 2 + h;
            int m = m0 + tm * 8 + i;
            int bidx = m >> 10, s = m & 1023;
            float4 o;
            o.x = (h ? c0.y : c0.x) + b4.x;
            o.y = (h ? c1.y : c1.x) + b4.y;
            o.z = (h ? c2.y : c2.x) + b4.z;
            o.w = (h ? c3.y : c3.x) + b4.w;
            *(float4*)(dst + (((size_t)(bidx * NH + head) * SEQ + s) * HD) + tn * 4) = o;
        }
    }
}

// ---------------------------------------------------------------------------
// Kernel 2: fused attention.
// Score phase: diagonal-aligned warp mapping (lanes of a warp share the
//   e-diagonal group) -> e-loads are warp-broadcast. Writes RAW scores to sP.
// Softmax pass: (lp, j=r-quarter) mapping, shfl over 4-lane group; exps 16
//   values/thread; p overwrites sP in place; mrun/lsum/corr thread-local.
// PV phase: (lp, j=d-quarter) as before.
// ---------------------------------------------------------------------------
constexpr int TL  = 64;
constexpr int TR  = 64;
constexpr int EPP = 68;  // sP row stride

constexpr size_t SMEM_FLOATS =
    (size_t)64 * 64      // sQ (swizzled)
  + (size_t)64 * 64      // sK (swizzled)
  + (size_t)128 * 64     // sE (swizzled, 127 rows used)
  + (size_t)64 * 64      // sV (plain)
  + (size_t)64 * EPP     // sP (raw scores, then p)
  + 64;                  // sM (mask)
constexpr size_t SMEM_BYTES = SMEM_FLOATS * 4;

__device__ __forceinline__ int swz(int row, int chunk) {
    return row * 64 + (((chunk ^ (row >> 2)) & 15) << 2);
}

__global__ __launch_bounds__(256, 2)
void attn_kernel(const float* __restrict__ E, const float* __restrict__ mask,
                 float* __restrict__ out) {
    extern __shared__ float sm[];
    float* sQ = sm;
    float* sK = sQ + 64 * 64;
    float* sE = sK + 64 * 64;
    float* sV = sE + 128 * 64;
    float* sP = sV + 64 * 64;
    float* sM = sP + 64 * EPP;

    const int bh   = blockIdx.y;
    const int b    = bh >> 4;
    const int head = bh & 15;
    const int l0   = blockIdx.x * TL;
    const int tid  = threadIdx.x;

    // score-phase mapping: lanes of a warp share diagonal group
    const int w    = tid >> 5;
    const int lam  = tid & 31;
    const int rg   = lam & 15;
    const int dgrp = 2 * w + (lam >> 4);          // 0..15
    const int lg   = (rg + dgrp) & 15;
    const int diag4 = 4 * (lg - rg);              // 4*diag, diag in [-15,15]

    // softmax/PV mapping
    const int lp = tid >> 2;
    const int j  = tid & 3;

    const float* Qg = g_Q + (size_t)bh * SEQ * HD;
    const float* Kg = g_K + (size_t)bh * SEQ * HD;
    const float* Vg = g_V + (size_t)bh * SEQ * HD;

    // Load Q tile once (swizzled)
#pragma unroll
    for (int p = 0; p < 4; p++) {
        int idx = tid + p * 256;
        int row = idx >> 4, c = idx & 15;
        *(float4*)(sQ + swz(row, c)) =
            *(const float4*)(Qg + (size_t)(l0 + row) * HD + c * 4);
    }

    u64 o2[8];
#pragma unroll
    for (int i = 0; i < 8; i++) o2[i] = 0ull;
    float mrun = -1e30f, lsum = 0.f;

    for (int t = 0; t < SEQ / TR; t++) {
        const int r0 = t * TR;
        __syncthreads();   // prev PV done with sP/sV before refill

        // Fill K (swizzled), V (plain)
#pragma unroll
        for (int p = 0; p < 4; p++) {
            int idx = tid + p * 256;
            int row = idx >> 4, c = idx & 15;
            *(float4*)(sK + swz(row, c)) =
                *(const float4*)(Kg + (size_t)(r0 + row) * HD + c * 4);
            *(float4*)(sV + row * 64 + c * 4) =
                *(const float4*)(Vg + (size_t)(r0 + row) * HD + c * 4);
        }
        // Fill E window (swizzled)
        const int base = l0 - r0 + 960;
        for (int idx = tid; idx < 127 * 16; idx += 256) {
            int ww = idx >> 4, c = idx & 15;
            *(float4*)(sE + swz(ww, c)) =
                *(const float4*)(E + (size_t)(base + ww) * HD + c * 4);
        }
        if (tid < TR) sM[tid] = mask[b * SEQ + r0 + tid];
        __syncthreads();

        // ---- score GEMM: acc2[il][ir] over d (f32x2 partial pairs)
        u64 acc2[4][4];
#pragma unroll
        for (int il = 0; il < 4; il++)
#pragma unroll
            for (int ir = 0; ir < 4; ir++) acc2[il][ir] = 0ull;

#pragma unroll 1
        for (int dc = 0; dc < 16; dc++) {
            const int qoff = (((dc ^ lg) & 15) << 2);
            const int koff = (((dc ^ rg) & 15) << 2);
            u64 qv[4][2], kv[4][2];
#pragma unroll
            for (int il = 0; il < 4; il++) {
                ulonglong2 v = *(const ulonglong2*)(sQ + (4 * lg + il) * 64 + qoff);
                qv[il][0] = v.x; qv[il][1] = v.y;
            }
#pragma unroll
            for (int ir = 0; ir < 4; ir++) {
                ulonglong2 v = *(const ulonglong2*)(sK + (4 * rg + ir) * 64 + koff);
                kv[ir][0] = v.x; kv[ir][1] = v.y;
            }
#pragma unroll
            for (int il = 0; il < 4; il++)
#pragma unroll
                for (int ir = 0; ir < 4; ir++) {
                    acc2[il][ir] = ffma2(qv[il][0], kv[ir][0], acc2[il][ir]);
                    acc2[il][ir] = ffma2(qv[il][1], kv[ir][1], acc2[il][ir]);
                }
            // positional term by diagonal: R = diag4 + dlt + 63 in [0,126]
            // lanes of this warp share <=4 distinct R per dlt -> broadcast
#pragma unroll
            for (int dlt = -3; dlt <= 3; dlt++) {
                int R = diag4 + dlt + 63;
                ulonglong2 e2 = *(const ulonglong2*)(
                    sE + R * 64 + ((((dc ^ (R >> 2)) & 15)) << 2));
#pragma unroll
                for (int il = 0; il < 4; il++) {
                    int ir = il - dlt;
                    if (ir >= 0 && ir < 4) {
                        u64 s0 = fadd2(qv[il][0], kv[ir][0]);
                        u64 s1 = fadd2(qv[il][1], kv[ir][1]);
                        acc2[il][ir] = ffma2(s0, e2.x, acc2[il][ir]);
                        acc2[il][ir] = ffma2(s1, e2.y, acc2[il][ir]);
                    }
                }
            }
        }

        // write raw scores to sP[l][4rg..4rg+4)
#pragma unroll
        for (int il = 0; il < 4; il++) {
            float2 h0 = unpack2(acc2[il][0]);
            float2 h1 = unpack2(acc2[il][1]);
            float2 h2 = unpack2(acc2[il][2]);
            float2 h3 = unpack2(acc2[il][3]);
            float4 sv = make_float4(h0.x + h0.y, h1.x + h1.y,
                                    h2.x + h2.y, h3.x + h3.y);
            *(float4*)(sP + (4 * lg + il) * EPP + 4 * rg) = sv;
        }
        __syncthreads();

        // ---- softmax pass: thread (lp, j) owns r-quarter [16j, 16j+16)
        {
            float* prow = sP + lp * EPP + j * 16;
            float s[16];
            float mt = -1e30f;
#pragma unroll
            for (int q = 0; q < 4; q++) {
                float4 sv = *(const float4*)(prow + q * 4);
                float4 mk = *(const float4*)(sM + j * 16 + q * 4);
                s[q * 4 + 0] = sv.x * 0.125f + mk.x;
                s[q * 4 + 1] = sv.y * 0.125f + mk.y;
                s[q * 4 + 2] = sv.z * 0.125f + mk.z;
                s[q * 4 + 3] = sv.w * 0.125f + mk.w;
                mt = fmaxf(mt, fmaxf(fmaxf(s[q*4+0], s[q*4+1]),
                                     fmaxf(s[q*4+2], s[q*4+3])));
            }
            mt = fmaxf(mt, __shfl_xor_sync(0xffffffffu, mt, 1));
            mt = fmaxf(mt, __shfl_xor_sync(0xffffffffu, mt, 2));
            float mnew = fmaxf(mrun, mt);
            float corr = __expf(mrun - mnew);
            float ps = 0.f;
#pragma unroll
            for (int q = 0; q < 4; q++) {
                float4 pv;
                pv.x = __expf(s[q*4+0] - mnew);
                pv.y = __expf(s[q*4+1] - mnew);
                pv.z = __expf(s[q*4+2] - mnew);
                pv.w = __expf(s[q*4+3] - mnew);
                *(float4*)(prow + q * 4) = pv;
                ps += pv.x + pv.y + pv.z + pv.w;
            }
            ps += __shfl_xor_sync(0xffffffffu, ps, 1);
            ps += __shfl_xor_sync(0xffffffffu, ps, 2);
            lsum = lsum * corr + ps;
            mrun = mnew;
            u64 c2 = pack2(corr, corr);
#pragma unroll
            for (int i = 0; i < 8; i++) o2[i] = fmul2(o2[i], c2);
        }
        __syncthreads();

        // ---- PV: thread (lp, j) owns d-quarter; o[d] += p[lp,r] * V[r,d]
        const float4* prow4 = (const float4*)(sP + lp * EPP);
#pragma unroll 4
        for (int r4 = 0; r4 < 16; r4++) {
            float4 p4 = prow4[r4];
            const float* vb = sV + (r4 * 4) * 64 + j * 16;
#pragma unroll
            for (int q = 0; q < 4; q++) {
                float pq = (q == 0) ? p4.x : (q == 1) ? p4.y : (q == 2) ? p4.z : p4.w;
                u64 pq2 = pack2(pq, pq);
                const ulonglong2* vr = (const ulonglong2*)(vb + q * 64);
                ulonglong2 va = vr[0], vbb = vr[1], vc = vr[2], vd = vr[3];
                o2[0] = ffma2(pq2, va.x,  o2[0]);
                o2[1] = ffma2(pq2, va.y,  o2[1]);
                o2[2] = ffma2(pq2, vbb.x, o2[2]);
                o2[3] = ffma2(pq2, vbb.y, o2[3]);
                o2[4] = ffma2(pq2, vc.x,  o2[4]);
                o2[5] = ffma2(pq2, vc.y,  o2[5]);
                o2[6] = ffma2(pq2, vd.x,  o2[6]);
                o2[7] = ffma2(pq2, vd.y,  o2[7]);
            }
        }
    }

    // epilogue: each (lp, j) thread holds its own lsum for row lp
    float inv = 1.f / lsum;
    float* op = out + ((size_t)(b * SEQ + l0 + lp) * HID) + head * HD + j * 16;
#pragma unroll
    for (int q = 0; q < 4; q++) {
        float2 lohi0 = unpack2(o2[q * 2 + 0]);
        float2 lohi1 = unpack2(o2[q * 2 + 1]);
        float4 vv = make_float4(lohi0.x * inv, lohi0.y * inv,
                                lohi1.x * inv, lohi1.y * inv);
        *(float4*)(op + q * 4) = vv;
    }
}

// ---------------------------------------------------------------------------
extern "C" void kernel_launch(void* const* d_in, const int* in_sizes, int n_in,
                              void* d_out, int out_size) {
    const float* X    = (const float*)d_in[0];   // hidden_states [4,1024,1024]
    const float* W    = (const float*)d_in[1];   // qkv_w [3072,1024]
    const float* bias = (const float*)d_in[2];   // qkv_b [3072]
    const float* E    = (const float*)d_in[3];   // dist_emb [2047,64]
    const float* msk  = (const float*)d_in[4];   // ext_mask [4,1,1,1024]
    float* out = (float*)d_out;

    dim3 g1(3 * HID / BN, (BB * SEQ) / BM);      // 48 x 32
    qkv_kernel<<<g1, 256>>>(X, W, bias);

    cudaFuncSetAttribute(attn_kernel,
                         cudaFuncAttributeMaxDynamicSharedMemorySize,
                         (int)SMEM_BYTES);
    dim3 g2(SEQ / TL, BH);                       // 16 x 64
    attn_kernel<<<g2, 256, SMEM_BYTES>>>(E, msk, out);
}

// round 8
// speedup vs baseline: 1.2325x; 1.2325x over previous
#include <cuda_runtime.h>
#include <cuda_bf16.h>
#include <cstdint>
#include <cstddef>

typedef unsigned long long u64;

// Problem constants
constexpr int SEQ  = 1024;
constexpr int HID  = 1024;
constexpr int NH   = 16;
constexpr int HD   = 64;
constexpr int BB   = 4;
constexpr int BH   = BB * NH;      // 64

// Scratch (head-major Q/K/V): [bh][s][d]
__device__ __align__(16) float g_Q[(size_t)BH * SEQ * HD];
__device__ __align__(16) float g_K[(size_t)BH * SEQ * HD];
__device__ __align__(16) float g_V[(size_t)BH * SEQ * HD];
// bf16 hi/lo splits of X and W
__device__ __align__(16) __nv_bfloat16 g_Xhi[(size_t)BB * SEQ * HID];
__device__ __align__(16) __nv_bfloat16 g_Xlo[(size_t)BB * SEQ * HID];
__device__ __align__(16) __nv_bfloat16 g_Whi[(size_t)3 * HID * HID];
__device__ __align__(16) __nv_bfloat16 g_Wlo[(size_t)3 * HID * HID];

// ---------------------------------------------------------------------------
// f32x2 helpers (attention kernel)
// ---------------------------------------------------------------------------
__device__ __forceinline__ u64 ffma2(u64 a, u64 b, u64 c) {
    u64 d;
    asm("fma.rn.f32x2 %0, %1, %2, %3;" : "=l"(d) : "l"(a), "l"(b), "l"(c));
    return d;
}
__device__ __forceinline__ u64 fadd2(u64 a, u64 b) {
    u64 d;
    asm("add.rn.f32x2 %0, %1, %2;" : "=l"(d) : "l"(a), "l"(b));
    return d;
}
__device__ __forceinline__ u64 fmul2(u64 a, u64 b) {
    u64 d;
    asm("mul.rn.f32x2 %0, %1, %2;" : "=l"(d) : "l"(a), "l"(b));
    return d;
}
__device__ __forceinline__ u64 pack2(float lo, float hi) {
    u64 d;
    asm("mov.b64 %0, {%1, %2};" : "=l"(d) : "f"(lo), "f"(hi));
    return d;
}
__device__ __forceinline__ float2 unpack2(u64 v) {
    float lo, hi;
    asm("mov.b64 {%0, %1}, %2;" : "=f"(lo), "=f"(hi) : "l"(v));
    return make_float2(lo, hi);
}

// ---------------------------------------------------------------------------
// mma.sync / ldmatrix / cp.async helpers (sm_80+ PTX, valid on sm_103)
// ---------------------------------------------------------------------------
__device__ __forceinline__ uint32_t smem_u32(const void* p) {
    uint32_t a;
    asm("{ .reg .u64 t; cvta.to.shared.u64 t, %1; cvt.u32.u64 %0, t; }"
        : "=r"(a) : "l"(p));
    return a;
}
__device__ __forceinline__ void ldsm4(uint32_t* r, uint32_t addr) {
    asm volatile("ldmatrix.sync.aligned.m8n8.x4.shared.b16 {%0,%1,%2,%3}, [%4];"
                 : "=r"(r[0]), "=r"(r[1]), "=r"(r[2]), "=r"(r[3]) : "r"(addr));
}
__device__ __forceinline__ void mma_bf16(float* c, const uint32_t* a,
                                         uint32_t b0, uint32_t b1) {
    asm volatile(
        "mma.sync.aligned.m16n8k16.row.col.f32.bf16.bf16.f32 "
        "{%0,%1,%2,%3}, {%4,%5,%6,%7}, {%8,%9}, {%0,%1,%2,%3};"
        : "+f"(c[0]), "+f"(c[1]), "+f"(c[2]), "+f"(c[3])
        : "r"(a[0]), "r"(a[1]), "r"(a[2]), "r"(a[3]), "r"(b0), "r"(b1));
}
__device__ __forceinline__ void cp16(uint32_t dst, const void* src) {
    asm volatile("cp.async.cg.shared.global [%0], [%1], 16;" :: "r"(dst), "l"(src));
}

// ---------------------------------------------------------------------------
// Kernel 0: split X, W into bf16 hi/lo
// ---------------------------------------------------------------------------
__global__ __launch_bounds__(256)
void split_kernel(const float* __restrict__ X, const float* __restrict__ W) {
    const size_t NX = (size_t)BB * SEQ * HID / 4;
    const size_t NW = (size_t)3 * HID * HID / 4;
    size_t i = (size_t)blockIdx.x * 256 + threadIdx.x;
    const float4* src;
    __nv_bfloat16 *hi, *lo;
    size_t off;
    if (i < NX)            { src = (const float4*)X; hi = g_Xhi; lo = g_Xlo; off = i; }
    else if (i < NX + NW)  { src = (const float4*)W; hi = g_Whi; lo = g_Wlo; off = i - NX; }
    else return;
    float4 v = src[off];
    ushort h[4], l[4];
    float vv[4] = {v.x, v.y, v.z, v.w};
#pragma unroll
    for (int q = 0; q < 4; q++) {
        __nv_bfloat16 hb = __float2bfloat16(vv[q]);
        float r = vv[q] - __bfloat162float(hb);
        __nv_bfloat16 lb = __float2bfloat16(r);
        h[q] = __bfloat16_as_ushort(hb);
        l[q] = __bfloat16_as_ushort(lb);
    }
    uint2 hp, lp;
    hp.x = (uint32_t)h[0] | ((uint32_t)h[1] << 16);
    hp.y = (uint32_t)h[2] | ((uint32_t)h[3] << 16);
    lp.x = (uint32_t)l[0] | ((uint32_t)l[1] << 16);
    lp.y = (uint32_t)l[2] | ((uint32_t)l[3] << 16);
    ((uint2*)hi)[off] = hp;
    ((uint2*)lo)[off] = lp;
}

// ---------------------------------------------------------------------------
// Kernel 1: QKV projection via mma.sync bf16x3.
// C[4096,3072] = X·Wᵀ + bias.  CTA 128x128, warps 2M x 4N (warp tile 64x32),
// K-chunks of 64 bf16 double-buffered with cp.async; head-major scatter.
// ---------------------------------------------------------------------------
constexpr int GM = 128;
constexpr int GN = 128;
constexpr int GK = 64;                 // 64 bf16 = 128 B rows
constexpr int NKT = HID / GK;          // 16
constexpr int ARR_B  = GM * GK * 2;    // 16384 bytes per matrix tile
constexpr int STAGE  = 4 * ARR_B;      // Ahi, Alo, Bhi, Blo = 65536
constexpr int QKV_SMEM = 2 * STAGE;    // 131072

__global__ __launch_bounds__(256, 1)
void qkv_mma_kernel(const float* __restrict__ bias) {
    extern __shared__ char smem[];
    const uint32_t sbase = smem_u32(smem);
    const int tid  = threadIdx.x;
    const int w    = tid >> 5;
    const int lane = tid & 31;
    const int wm   = w & 1;              // 0..1, 64 rows each
    const int wn   = w >> 1;             // 0..3, 32 cols each

    const int n0 = blockIdx.x * GN;
    const int m0 = blockIdx.y * GM;

    // --- async stage loader (16 cp.async per thread) ---
    auto load_stage = [&](int stg, int kt) {
        const int k0 = kt * GK;
        const uint32_t sb = sbase + stg * STAGE;
#pragma unroll
        for (int p = 0; p < 4; p++) {
            int ci = tid + p * 256;              // 0..1023 chunk index
            int r = ci >> 3, c = ci & 7;         // row, 16B-chunk
            uint32_t off = (uint32_t)(r * 128 + ((c ^ (r & 7)) * 16));
            size_t goA = (size_t)(m0 + r) * HID + k0 + c * 8;
            size_t goB = (size_t)(n0 + r) * HID + k0 + c * 8;
            cp16(sb + off,              g_Xhi + goA);
            cp16(sb + ARR_B + off,      g_Xlo + goA);
            cp16(sb + 2 * ARR_B + off,  g_Whi + goB);
            cp16(sb + 3 * ARR_B + off,  g_Wlo + goB);
        }
        asm volatile("cp.async.commit_group;");
    };

    float acc[4][4][4];
#pragma unroll
    for (int mt = 0; mt < 4; mt++)
#pragma unroll
        for (int nt = 0; nt < 4; nt++)
#pragma unroll
            for (int q = 0; q < 4; q++) acc[mt][nt][q] = 0.f;

    load_stage(0, 0);

    for (int kt = 0; kt < NKT; kt++) {
        const bool has_next = (kt + 1 < NKT);
        if (has_next) load_stage((kt + 1) & 1, kt + 1);
        if (has_next) asm volatile("cp.async.wait_group 1;");
        else          asm volatile("cp.async.wait_group 0;");
        __syncthreads();

        const uint32_t sAhi = sbase + (kt & 1) * STAGE;
        const uint32_t sAlo = sAhi + ARR_B;
        const uint32_t sBhi = sAhi + 2 * ARR_B;
        const uint32_t sBlo = sAhi + 3 * ARR_B;

#pragma unroll
        for (int ks = 0; ks < 4; ks++) {
            // B frags: 2 pairs x (hi, lo); regs [pair][4] = 2 n-tiles each
            uint32_t bhi[2][4], blo[2][4];
#pragma unroll
            for (int p2 = 0; p2 < 2; p2++) {
                int row = wn * 32 + p2 * 16 + (lane & 7) + ((lane >> 4) & 1) * 8;
                int c   = ks * 2 + ((lane >> 3) & 1);
                uint32_t off = (uint32_t)(row * 128 + ((c ^ (row & 7)) * 16));
                ldsm4(bhi[p2], sBhi + off);
                ldsm4(blo[p2], sBlo + off);
            }
#pragma unroll
            for (int mt = 0; mt < 4; mt++) {
                int row = wm * 64 + mt * 16 + (lane & 15);
                int c   = ks * 2 + (lane >> 4);
                uint32_t off = (uint32_t)(row * 128 + ((c ^ (row & 7)) * 16));
                uint32_t ahi[4], alo[4];
                ldsm4(ahi, sAhi + off);
                ldsm4(alo, sAlo + off);
#pragma unroll
                for (int nt = 0; nt < 4; nt++) {
                    int pr = nt >> 1, sub = nt & 1;
                    uint32_t b0h = bhi[pr][sub * 2], b1h = bhi[pr][sub * 2 + 1];
                    uint32_t b0l = blo[pr][sub * 2], b1l = blo[pr][sub * 2 + 1];
                    mma_bf16(acc[mt][nt], ahi, b0h, b1h);
                    mma_bf16(acc[mt][nt], ahi, b0l, b1l);
                    mma_bf16(acc[mt][nt], alo, b0h, b1h);
                }
            }
        }
        __syncthreads();
    }

    // --- epilogue: bias + head-major scatter ---
#pragma unroll
    for (int nt = 0; nt < 4; nt++) {
        const int col0 = n0 + wn * 32 + nt * 8 + (lane & 3) * 2;
        const int part = col0 >> 10;
        const int rem  = col0 & 1023;
        const int head = rem >> 6;
        const int d    = rem & 63;
        float* dstb = (part == 0) ? g_Q : (part == 1) ? g_K : g_V;
        float2 b2 = *(const float2*)(bias + col0);
#pragma unroll
        for (int mt = 0; mt < 4; mt++) {
            int row0 = m0 + wm * 64 + mt * 16 + (lane >> 2);
#pragma unroll
            for (int h = 0; h < 2; h++) {
                int row = row0 + h * 8;
                int bq = row >> 10, s = row & 1023;
                float2 o;
                o.x = acc[mt][nt][h * 2 + 0] + b2.x;
                o.y = acc[mt][nt][h * 2 + 1] + b2.y;
                *(float2*)(dstb + (((size_t)(bq * NH + head) * SEQ + s) * HD) + d) = o;
            }
        }
    }
}

// ---------------------------------------------------------------------------
// Kernel 2: fused attention (R4 variant — best measured: 1552us)
// ---------------------------------------------------------------------------
constexpr int TL  = 64;
constexpr int TR  = 64;
constexpr int EPP = 68;

constexpr size_t SMEM_FLOATS =
    (size_t)64 * 64 + (size_t)64 * 64 + (size_t)128 * 64 + (size_t)64 * 64
  + (size_t)64 * EPP + 64 + 64;
constexpr size_t SMEM_BYTES = SMEM_FLOATS * 4;

__device__ __forceinline__ int swz(int row, int chunk) {
    return row * 64 + (((chunk ^ (row >> 2)) & 15) << 2);
}

__global__ __launch_bounds__(256, 2)
void attn_kernel(const float* __restrict__ E, const float* __restrict__ mask,
                 float* __restrict__ out) {
    extern __shared__ float sm[];
    float* sQ = sm;
    float* sK = sQ + 64 * 64;
    float* sE = sK + 64 * 64;
    float* sV = sE + 128 * 64;
    float* sP = sV + 64 * 64;
    float* sM = sP + 64 * EPP;
    float* sC = sM + 64;

    const int bh   = blockIdx.y;
    const int b    = bh >> 4;
    const int head = bh & 15;
    const int l0   = blockIdx.x * TL;
    const int tid  = threadIdx.x;
    const int lg = tid >> 4;
    const int rg = tid & 15;
    const int diag4 = 4 * (lg - rg);
    const int lp = tid >> 2;
    const int j  = tid & 3;

    const float* Qg = g_Q + (size_t)bh * SEQ * HD;
    const float* Kg = g_K + (size_t)bh * SEQ * HD;
    const float* Vg = g_V + (size_t)bh * SEQ * HD;

#pragma unroll
    for (int p = 0; p < 4; p++) {
        int idx = tid + p * 256;
        int row = idx >> 4, c = idx & 15;
        *(float4*)(sQ + swz(row, c)) =
            *(const float4*)(Qg + (size_t)(l0 + row) * HD + c * 4);
    }

    u64 o2[8];
#pragma unroll
    for (int i = 0; i < 8; i++) o2[i] = 0ull;
    float mrun[4], lsum[4];
#pragma unroll
    for (int i = 0; i < 4; i++) { mrun[i] = -1e30f; lsum[i] = 0.f; }

    for (int t = 0; t < SEQ / TR; t++) {
        const int r0 = t * TR;
        __syncthreads();

#pragma unroll
        for (int p = 0; p < 4; p++) {
            int idx = tid + p * 256;
            int row = idx >> 4, c = idx & 15;
            *(float4*)(sK + swz(row, c)) =
                *(const float4*)(Kg + (size_t)(r0 + row) * HD + c * 4);
            *(float4*)(sV + row * 64 + c * 4) =
                *(const float4*)(Vg + (size_t)(r0 + row) * HD + c * 4);
        }
        const int base = l0 - r0 + 960;
        for (int idx = tid; idx < 127 * 16; idx += 256) {
            int ww = idx >> 4, c = idx & 15;
            *(float4*)(sE + swz(ww, c)) =
                *(const float4*)(E + (size_t)(base + ww) * HD + c * 4);
        }
        if (tid < TR) sM[tid] = mask[b * SEQ + r0 + tid];
        __syncthreads();

        u64 acc2[4][4];
#pragma unroll
        for (int il = 0; il < 4; il++)
#pragma unroll
            for (int ir = 0; ir < 4; ir++) acc2[il][ir] = 0ull;

#pragma unroll 1
        for (int dc = 0; dc < 16; dc++) {
            const int qoff = (((dc ^ lg) & 15) << 2);
            const int koff = (((dc ^ rg) & 15) << 2);
            u64 qv[4][2], kv[4][2];
#pragma unroll
            for (int il = 0; il < 4; il++) {
                ulonglong2 v = *(const ulonglong2*)(sQ + (4 * lg + il) * 64 + qoff);
                qv[il][0] = v.x; qv[il][1] = v.y;
            }
#pragma unroll
            for (int ir = 0; ir < 4; ir++) {
                ulonglong2 v = *(const ulonglong2*)(sK + (4 * rg + ir) * 64 + koff);
                kv[ir][0] = v.x; kv[ir][1] = v.y;
            }
#pragma unroll
            for (int il = 0; il < 4; il++)
#pragma unroll
                for (int ir = 0; ir < 4; ir++) {
                    acc2[il][ir] = ffma2(qv[il][0], kv[ir][0], acc2[il][ir]);
                    acc2[il][ir] = ffma2(qv[il][1], kv[ir][1], acc2[il][ir]);
                }
#pragma unroll
            for (int dlt = -3; dlt <= 3; dlt++) {
                int R = diag4 + dlt + 63;
                ulonglong2 e2 = *(const ulonglong2*)(
                    sE + R * 64 + ((((dc ^ (R >> 2)) & 15)) << 2));
#pragma unroll
                for (int il = 0; il < 4; il++) {
                    int ir = il - dlt;
                    if (ir >= 0 && ir < 4) {
                        u64 s0 = fadd2(qv[il][0], kv[ir][0]);
                        u64 s1 = fadd2(qv[il][1], kv[ir][1]);
                        acc2[il][ir] = ffma2(s0, e2.x, acc2[il][ir]);
                        acc2[il][ir] = ffma2(s1, e2.y, acc2[il][ir]);
                    }
                }
            }
        }

        float4 mk = *(const float4*)(sM + 4 * rg);
        float corr[4];
#pragma unroll
        for (int il = 0; il < 4; il++) {
            float s[4];
            float mt = -1e30f;
#pragma unroll
            for (int ir = 0; ir < 4; ir++) {
                float2 h = unpack2(acc2[il][ir]);
                float msk = (ir == 0) ? mk.x : (ir == 1) ? mk.y : (ir == 2) ? mk.z : mk.w;
                s[ir] = (h.x + h.y) * 0.125f + msk;
                mt = fmaxf(mt, s[ir]);
            }
            mt = fmaxf(mt, __shfl_xor_sync(0xffffffffu, mt, 1));
            mt = fmaxf(mt, __shfl_xor_sync(0xffffffffu, mt, 2));
            mt = fmaxf(mt, __shfl_xor_sync(0xffffffffu, mt, 4));
            mt = fmaxf(mt, __shfl_xor_sync(0xffffffffu, mt, 8));
            float mnew = fmaxf(mrun[il], mt);
            corr[il] = __expf(mrun[il] - mnew);
            float4 pv;
            pv.x = __expf(s[0] - mnew);
            pv.y = __expf(s[1] - mnew);
            pv.z = __expf(s[2] - mnew);
            pv.w = __expf(s[3] - mnew);
            *(float4*)(sP + (4 * lg + il) * EPP + 4 * rg) = pv;
            float ps = pv.x + pv.y + pv.z + pv.w;
            ps += __shfl_xor_sync(0xffffffffu, ps, 1);
            ps += __shfl_xor_sync(0xffffffffu, ps, 2);
            ps += __shfl_xor_sync(0xffffffffu, ps, 4);
            ps += __shfl_xor_sync(0xffffffffu, ps, 8);
            lsum[il] = lsum[il] * corr[il] + ps;
            mrun[il] = mnew;
        }
        if (rg == 0) {
#pragma unroll
            for (int il = 0; il < 4; il++) sC[4 * lg + il] = corr[il];
        }
        __syncthreads();

        {
            float cv = sC[lp];
            u64 c2 = pack2(cv, cv);
#pragma unroll
            for (int i = 0; i < 8; i++) o2[i] = fmul2(o2[i], c2);
        }
        const float4* prow = (const float4*)(sP + lp * EPP);
#pragma unroll 4
        for (int r4 = 0; r4 < 16; r4++) {
            float4 p4 = prow[r4];
            const float* vb = sV + (r4 * 4) * 64 + j * 16;
#pragma unroll
            for (int q = 0; q < 4; q++) {
                float pq = (q == 0) ? p4.x : (q == 1) ? p4.y : (q == 2) ? p4.z : p4.w;
                u64 pq2 = pack2(pq, pq);
                const ulonglong2* vr = (const ulonglong2*)(vb + q * 64);
                ulonglong2 va = vr[0], vbb = vr[1], vc = vr[2], vd = vr[3];
                o2[0] = ffma2(pq2, va.x,  o2[0]);
                o2[1] = ffma2(pq2, va.y,  o2[1]);
                o2[2] = ffma2(pq2, vbb.x, o2[2]);
                o2[3] = ffma2(pq2, vbb.y, o2[3]);
                o2[4] = ffma2(pq2, vc.x,  o2[4]);
                o2[5] = ffma2(pq2, vc.y,  o2[5]);
                o2[6] = ffma2(pq2, vd.x,  o2[6]);
                o2[7] = ffma2(pq2, vd.y,  o2[7]);
            }
        }
    }

    __syncthreads();
    if (rg == 0) {
#pragma unroll
        for (int il = 0; il < 4; il++) sC[4 * lg + il] = 1.f / lsum[il];
    }
    __syncthreads();
    float inv = sC[lp];

    float* op = out + ((size_t)(b * SEQ + l0 + lp) * HID) + head * HD + j * 16;
#pragma unroll
    for (int q = 0; q < 4; q++) {
        float2 lohi0 = unpack2(o2[q * 2 + 0]);
        float2 lohi1 = unpack2(o2[q * 2 + 1]);
        float4 vv = make_float4(lohi0.x * inv, lohi0.y * inv,
                                lohi1.x * inv, lohi1.y * inv);
        *(float4*)(op + q * 4) = vv;
    }
}

// ---------------------------------------------------------------------------
extern "C" void kernel_launch(void* const* d_in, const int* in_sizes, int n_in,
                              void* d_out, int out_size) {
    const float* X    = (const float*)d_in[0];   // hidden_states [4,1024,1024]
    const float* W    = (const float*)d_in[1];   // qkv_w [3072,1024]
    const float* bias = (const float*)d_in[2];   // qkv_b [3072]
    const float* E    = (const float*)d_in[3];   // dist_emb [2047,64]
    const float* msk  = (const float*)d_in[4];   // ext_mask [4,1,1,1024]
    float* out = (float*)d_out;

    // 0. split to bf16 hi/lo
    const size_t NV = ((size_t)BB * SEQ * HID + (size_t)3 * HID * HID) / 4;
    split_kernel<<<(unsigned)((NV + 255) / 256), 256>>>(X, W);

    // 1. QKV via mma.sync bf16x3
    cudaFuncSetAttribute(qkv_mma_kernel,
                         cudaFuncAttributeMaxDynamicSharedMemorySize, QKV_SMEM);
    dim3 g1(3 * HID / GN, (BB * SEQ) / GM);      // 24 x 32
    qkv_mma_kernel<<<g1, 256, QKV_SMEM>>>(bias);

    // 2. attention
    cudaFuncSetAttribute(attn_kernel,
                         cudaFuncAttributeMaxDynamicSharedMemorySize,
                         (int)SMEM_BYTES);
    dim3 g2(SEQ / TL, BH);                       // 16 x 64
    attn_kernel<<<g2, 256, SMEM_BYTES>>>(E, msk, out);
}

// round 9
// speedup vs baseline: 3.0385x; 2.4654x over previous
#include <cuda_runtime.h>
#include <cuda_bf16.h>
#include <cstdint>
#include <cstddef>

typedef unsigned long long u64;

// Problem constants
constexpr int SEQ  = 1024;
constexpr int HID  = 1024;
constexpr int NH   = 16;
constexpr int HD   = 64;
constexpr int BB   = 4;
constexpr int BH   = BB * NH;      // 64
constexpr int EROWS = 2 * 1024 - 1; // 2047

// bf16 hi/lo splits (inputs + intermediates), all head-major for Q/K/V
__device__ __align__(16) __nv_bfloat16 g_Xhi[(size_t)BB * SEQ * HID];
__device__ __align__(16) __nv_bfloat16 g_Xlo[(size_t)BB * SEQ * HID];
__device__ __align__(16) __nv_bfloat16 g_Whi[(size_t)3 * HID * HID];
__device__ __align__(16) __nv_bfloat16 g_Wlo[(size_t)3 * HID * HID];
__device__ __align__(16) __nv_bfloat16 g_Ehi[(size_t)EROWS * HD];
__device__ __align__(16) __nv_bfloat16 g_Qhi[(size_t)BH * SEQ * HD];
__device__ __align__(16) __nv_bfloat16 g_Qlo[(size_t)BH * SEQ * HD];
__device__ __align__(16) __nv_bfloat16 g_Khi[(size_t)BH * SEQ * HD];
__device__ __align__(16) __nv_bfloat16 g_Klo[(size_t)BH * SEQ * HD];
__device__ __align__(16) __nv_bfloat16 g_Vhi[(size_t)BH * SEQ * HD];
__device__ __align__(16) __nv_bfloat16 g_Vlo[(size_t)BH * SEQ * HD];

// ---------------------------------------------------------------------------
// mma.sync / ldmatrix / cp.async helpers (sm_80+ PTX, valid on sm_103)
// ---------------------------------------------------------------------------
__device__ __forceinline__ uint32_t smem_u32(const void* p) {
    uint32_t a;
    asm("{ .reg .u64 t; cvta.to.shared.u64 t, %1; cvt.u32.u64 %0, t; }"
        : "=r"(a) : "l"(p));
    return a;
}
__device__ __forceinline__ void ldsm4(uint32_t* r, uint32_t addr) {
    asm volatile("ldmatrix.sync.aligned.m8n8.x4.shared.b16 {%0,%1,%2,%3}, [%4];"
                 : "=r"(r[0]), "=r"(r[1]), "=r"(r[2]), "=r"(r[3]) : "r"(addr));
}
__device__ __forceinline__ void ldsm4t(uint32_t* r, uint32_t addr) {
    asm volatile("ldmatrix.sync.aligned.m8n8.x4.trans.shared.b16 {%0,%1,%2,%3}, [%4];"
                 : "=r"(r[0]), "=r"(r[1]), "=r"(r[2]), "=r"(r[3]) : "r"(addr));
}
__device__ __forceinline__ void mma_bf16(float* c, const uint32_t* a,
                                         uint32_t b0, uint32_t b1) {
    asm volatile(
        "mma.sync.aligned.m16n8k16.row.col.f32.bf16.bf16.f32 "
        "{%0,%1,%2,%3}, {%4,%5,%6,%7}, {%8,%9}, {%0,%1,%2,%3};"
        : "+f"(c[0]), "+f"(c[1]), "+f"(c[2]), "+f"(c[3])
        : "r"(a[0]), "r"(a[1]), "r"(a[2]), "r"(a[3]), "r"(b0), "r"(b1));
}
__device__ __forceinline__ void cp16(uint32_t dst, const void* src) {
    asm volatile("cp.async.cg.shared.global [%0], [%1], 16;" :: "r"(dst), "l"(src));
}
// swizzled byte offset for (row, 16B-chunk) in a 128B-row matrix
__device__ __forceinline__ int SWB(int r, int c) {
    return r * 128 + (((c ^ (r & 7))) << 4);
}
__device__ __forceinline__ uint32_t bf2u32(float a, float b) {
    __nv_bfloat162 v = __floats2bfloat162_rn(a, b);
    return *(uint32_t*)&v;
}

// ---------------------------------------------------------------------------
// Kernel 0: split X, W into bf16 hi/lo; convert E to bf16 hi
// ---------------------------------------------------------------------------
__global__ __launch_bounds__(256)
void split_kernel(const float* __restrict__ X, const float* __restrict__ W,
                  const float* __restrict__ E) {
    const size_t NX = (size_t)BB * SEQ * HID / 4;
    const size_t NW = (size_t)3 * HID * HID / 4;
    const size_t NE = (size_t)EROWS * HD / 4;
    size_t i = (size_t)blockIdx.x * 256 + threadIdx.x;
    if (i < NX + NW) {
        const float4* src;
        __nv_bfloat16 *hi, *lo;
        size_t off;
        if (i < NX) { src = (const float4*)X; hi = g_Xhi; lo = g_Xlo; off = i; }
        else        { src = (const float4*)W; hi = g_Whi; lo = g_Wlo; off = i - NX; }
        float4 v = src[off];
        float vv[4] = {v.x, v.y, v.z, v.w};
        ushort h[4], l[4];
#pragma unroll
        for (int q = 0; q < 4; q++) {
            __nv_bfloat16 hb = __float2bfloat16(vv[q]);
            __nv_bfloat16 lb = __float2bfloat16(vv[q] - __bfloat162float(hb));
            h[q] = __bfloat16_as_ushort(hb);
            l[q] = __bfloat16_as_ushort(lb);
        }
        uint2 hp, lp;
        hp.x = (uint32_t)h[0] | ((uint32_t)h[1] << 16);
        hp.y = (uint32_t)h[2] | ((uint32_t)h[3] << 16);
        lp.x = (uint32_t)l[0] | ((uint32_t)l[1] << 16);
        lp.y = (uint32_t)l[2] | ((uint32_t)l[3] << 16);
        ((uint2*)hi)[off] = hp;
        ((uint2*)lo)[off] = lp;
    } else if (i < NX + NW + NE) {
        size_t off = i - NX - NW;
        float4 v = ((const float4*)E)[off];
        uint2 hp;
        hp.x = (uint32_t)__bfloat16_as_ushort(__float2bfloat16(v.x))
             | ((uint32_t)__bfloat16_as_ushort(__float2bfloat16(v.y)) << 16);
        hp.y = (uint32_t)__bfloat16_as_ushort(__float2bfloat16(v.z))
             | ((uint32_t)__bfloat16_as_ushort(__float2bfloat16(v.w)) << 16);
        ((uint2*)g_Ehi)[off] = hp;
    }
}

// ---------------------------------------------------------------------------
// Kernel 1: QKV projection via mma.sync bf16x3 -> bf16 hi/lo head-major out
// ---------------------------------------------------------------------------
constexpr int GM = 128;
constexpr int GN = 128;
constexpr int GK = 64;
constexpr int NKT = HID / GK;
constexpr int ARR_B  = GM * GK * 2;
constexpr int STAGE  = 4 * ARR_B;
constexpr int QKV_SMEM = 2 * STAGE;

__global__ __launch_bounds__(256, 1)
void qkv_mma_kernel(const float* __restrict__ bias) {
    extern __shared__ char smem[];
    const uint32_t sbase = smem_u32(smem);
    const int tid  = threadIdx.x;
    const int w    = tid >> 5;
    const int lane = tid & 31;
    const int wm   = w & 1;
    const int wn   = w >> 1;

    const int n0 = blockIdx.x * GN;
    const int m0 = blockIdx.y * GM;

    auto load_stage = [&](int stg, int kt) {
        const int k0 = kt * GK;
        const uint32_t sb = sbase + stg * STAGE;
#pragma unroll
        for (int p = 0; p < 4; p++) {
            int ci = tid + p * 256;
            int r = ci >> 3, c = ci & 7;
            uint32_t off = (uint32_t)(r * 128 + ((c ^ (r & 7)) * 16));
            size_t goA = (size_t)(m0 + r) * HID + k0 + c * 8;
            size_t goB = (size_t)(n0 + r) * HID + k0 + c * 8;
            cp16(sb + off,              g_Xhi + goA);
            cp16(sb + ARR_B + off,      g_Xlo + goA);
            cp16(sb + 2 * ARR_B + off,  g_Whi + goB);
            cp16(sb + 3 * ARR_B + off,  g_Wlo + goB);
        }
        asm volatile("cp.async.commit_group;");
    };

    float acc[4][4][4];
#pragma unroll
    for (int mt = 0; mt < 4; mt++)
#pragma unroll
        for (int nt = 0; nt < 4; nt++)
#pragma unroll
            for (int q = 0; q < 4; q++) acc[mt][nt][q] = 0.f;

    load_stage(0, 0);

    for (int kt = 0; kt < NKT; kt++) {
        const bool has_next = (kt + 1 < NKT);
        if (has_next) load_stage((kt + 1) & 1, kt + 1);
        if (has_next) asm volatile("cp.async.wait_group 1;");
        else          asm volatile("cp.async.wait_group 0;");
        __syncthreads();

        const uint32_t sAhi = sbase + (kt & 1) * STAGE;
        const uint32_t sAlo = sAhi + ARR_B;
        const uint32_t sBhi = sAhi + 2 * ARR_B;
        const uint32_t sBlo = sAhi + 3 * ARR_B;

#pragma unroll
        for (int ks = 0; ks < 4; ks++) {
            uint32_t bhi[2][4], blo[2][4];
#pragma unroll
            for (int p2 = 0; p2 < 2; p2++) {
                int row = wn * 32 + p2 * 16 + (lane & 7) + ((lane >> 4) & 1) * 8;
                int c   = ks * 2 + ((lane >> 3) & 1);
                uint32_t off = (uint32_t)(row * 128 + ((c ^ (row & 7)) * 16));
                ldsm4(bhi[p2], sBhi + off);
                ldsm4(blo[p2], sBlo + off);
            }
#pragma unroll
            for (int mt = 0; mt < 4; mt++) {
                int row = wm * 64 + mt * 16 + (lane & 15);
                int c   = ks * 2 + (lane >> 4);
                uint32_t off = (uint32_t)(row * 128 + ((c ^ (row & 7)) * 16));
                uint32_t ahi[4], alo[4];
                ldsm4(ahi, sAhi + off);
                ldsm4(alo, sAlo + off);
#pragma unroll
                for (int nt = 0; nt < 4; nt++) {
                    int pr = nt >> 1, sub = nt & 1;
                    uint32_t b0h = bhi[pr][sub * 2], b1h = bhi[pr][sub * 2 + 1];
                    uint32_t b0l = blo[pr][sub * 2], b1l = blo[pr][sub * 2 + 1];
                    mma_bf16(acc[mt][nt], ahi, b0h, b1h);
                    mma_bf16(acc[mt][nt], ahi, b0l, b1l);
                    mma_bf16(acc[mt][nt], alo, b0h, b1h);
                }
            }
        }
        __syncthreads();
    }

    // epilogue: bias + hi/lo split + head-major scatter (bf16)
#pragma unroll
    for (int nt = 0; nt < 4; nt++) {
        const int col0 = n0 + wn * 32 + nt * 8 + (lane & 3) * 2;
        const int part = col0 >> 10;
        const int rem  = col0 & 1023;
        const int head = rem >> 6;
        const int d    = rem & 63;
        __nv_bfloat16* dhi = (part == 0) ? g_Qhi : (part == 1) ? g_Khi : g_Vhi;
        __nv_bfloat16* dlo = (part == 0) ? g_Qlo : (part == 1) ? g_Klo : g_Vlo;
        float2 b2 = *(const float2*)(bias + col0);
#pragma unroll
        for (int mt = 0; mt < 4; mt++) {
            int row0 = m0 + wm * 64 + mt * 16 + (lane >> 2);
#pragma unroll
            for (int h = 0; h < 2; h++) {
                int row = row0 + h * 8;
                int bq = row >> 10, s = row & 1023;
                float ox = acc[mt][nt][h * 2 + 0] + b2.x;
                float oy = acc[mt][nt][h * 2 + 1] + b2.y;
                __nv_bfloat16 hx = __float2bfloat16(ox);
                __nv_bfloat16 hy = __float2bfloat16(oy);
                float lx = ox - __bfloat162float(hx);
                float ly = oy - __bfloat162float(hy);
                size_t idx = ((size_t)(bq * NH + head) * SEQ + s) * HD + d;
                *(uint32_t*)(dhi + idx) =
                    (uint32_t)__bfloat16_as_ushort(hx)
                  | ((uint32_t)__bfloat16_as_ushort(hy) << 16);
                *(uint32_t*)(dlo + idx) =
                    (uint32_t)__bfloat16_as_ushort(__float2bfloat16(lx))
                  | ((uint32_t)__bfloat16_as_ushort(__float2bfloat16(ly)) << 16);
            }
        }
    }
}

// ---------------------------------------------------------------------------
// Kernel 2: fused attention, fully tensorized.
// S = Q·Kᵀ (x3), T1 = Qhi·Ehiᵀ, T2 = Khi·Ehiᵀ (E window 127 rows, padded 128),
// score = (S + T1[l,l-r+63] + T2[r,l-r+63])/8 + mask; softmax; O += P·V (x3).
// ---------------------------------------------------------------------------
constexpr int O_QHI = 0;
constexpr int O_QLO = 8192;
constexpr int O_KHI = 16384;
constexpr int O_KLO = 24576;
constexpr int O_VHI = 32768;
constexpr int O_VLO = 40960;
constexpr int O_T1  = 49152;   // 64x128 bf16; overlaid by P_hi (64x64 bf16)
constexpr int O_T2  = 65536;   // 64x128 bf16; overlaid by P_lo
constexpr int O_ES  = 81920;   // E window bf16 (128x64) / S fp32 (64x66)
constexpr int O_M   = 98816;
constexpr int O_C   = 99072;
constexpr int O_L   = 99328;
constexpr int ATT_SMEM = 99584;

__global__ __launch_bounds__(256, 2)
void attn_mma_kernel(const float* __restrict__ mask, float* __restrict__ out) {
    extern __shared__ char smem[];
    const uint32_t sb = smem_u32(smem);
    const int tid  = threadIdx.x;
    const int wid  = tid >> 5;
    const int lane = tid & 31;
    const int bh   = blockIdx.y;
    const int b    = bh >> 4;
    const int head = bh & 15;
    const int l0   = blockIdx.x * 64;
    const int sm0  = 16 * (wid & 3);
    const int sn0  = 32 * (wid >> 2);
    const int en0  = 64 * (wid >> 2);
    const int lp   = tid >> 2;
    const int j    = tid & 3;
    const size_t hb = (size_t)bh * SEQ * HD;

    // frag loaders (byte-offset base within smem)
    auto LDA = [&](uint32_t* f, int obase, int m0, int ks) {
        int row = m0 + (lane & 15);
        int c   = ks * 2 + (lane >> 4);
        ldsm4(f, sb + obase + SWB(row, c));
    };
    auto LDB = [&](uint32_t* f, int obase, int n0, int ks) {
        int row = n0 + (lane & 7) + (((lane >> 4) & 1) << 3);
        int c   = ks * 2 + ((lane >> 3) & 1);
        ldsm4(f, sb + obase + SWB(row, c));
    };
    auto LDBT = [&](uint32_t* f, int obase, int k0, int ncol) {
        int row = k0 + (lane & 7) + (((lane >> 3) & 1) << 3);
        int c   = (ncol >> 3) + ((lane >> 4) & 1);
        ldsm4t(f, sb + obase + SWB(row, c));
    };

    // load Q hi/lo tiles once
#pragma unroll
    for (int p = 0; p < 4; p++) {
        int ci = tid + p * 256;
        int m = ci >> 9, cj = ci & 511, r = cj >> 3, c = cj & 7;
        const __nv_bfloat16* src = ((m == 0) ? g_Qhi : g_Qlo)
                                   + hb + (size_t)(l0 + r) * HD + c * 8;
        *(uint4*)(smem + O_QHI + m * 8192 + SWB(r, c)) = *(const uint4*)src;
    }

    float Oa[4][4];
#pragma unroll
    for (int nt = 0; nt < 4; nt++)
#pragma unroll
        for (int q = 0; q < 4; q++) Oa[nt][q] = 0.f;
    float mrun = -1e30f, lsum = 0.f;

    for (int t = 0; t < 16; t++) {
        const int r0 = t * 64;
        __syncthreads();   // B1: prev PV done with P/V

        // load K/V hi/lo
#pragma unroll
        for (int p = 0; p < 8; p++) {
            int ci = tid + p * 256;
            int m = ci >> 9, cj = ci & 511, r = cj >> 3, c = cj & 7;
            const __nv_bfloat16* base =
                (m == 0) ? g_Khi : (m == 1) ? g_Klo : (m == 2) ? g_Vhi : g_Vlo;
            const __nv_bfloat16* src = base + hb + (size_t)(r0 + r) * HD + c * 8;
            *(uint4*)(smem + O_KHI + m * 8192 + SWB(r, c)) = *(const uint4*)src;
        }
        // load E window (127 rows; row 127 garbage, never gathered)
        const int base = l0 - r0 + 960;
        for (int idx = tid; idx < 127 * 8; idx += 256) {
            int ww = idx >> 3, c = idx & 7;
            *(uint4*)(smem + O_ES + SWB(ww, c)) =
                *(const uint4*)(g_Ehi + (size_t)(base + ww) * HD + c * 8);
        }
        if (tid < 64) ((float*)(smem + O_M))[tid] = mask[b * SEQ + r0 + tid];
        __syncthreads();   // B2: tiles visible

        // ---- S = Q·Kᵀ (3 products)
        float Sa[4][4];
#pragma unroll
        for (int nt = 0; nt < 4; nt++)
#pragma unroll
            for (int q = 0; q < 4; q++) Sa[nt][q] = 0.f;
#pragma unroll
        for (int ks = 0; ks < 4; ks++) {
            uint32_t ahi[4], alo[4], b0h[4], b1h[4], b0l[4], b1l[4];
            LDA(ahi, O_QHI, sm0, ks); LDA(alo, O_QLO, sm0, ks);
            LDB(b0h, O_KHI, sn0, ks); LDB(b1h, O_KHI, sn0 + 16, ks);
            LDB(b0l, O_KLO, sn0, ks); LDB(b1l, O_KLO, sn0 + 16, ks);
#pragma unroll
            for (int nt = 0; nt < 4; nt++) {
                uint32_t* bh_ = (nt < 2) ? b0h : b1h;
                uint32_t* bl_ = (nt < 2) ? b0l : b1l;
                int s2 = (nt & 1) * 2;
                mma_bf16(Sa[nt], ahi, bh_[s2], bh_[s2 + 1]);
                mma_bf16(Sa[nt], ahi, bl_[s2], bl_[s2 + 1]);
                mma_bf16(Sa[nt], alo, bh_[s2], bh_[s2 + 1]);
            }
        }

        // ---- T1 = Qhi·Ehiᵀ, write bf16; then T2 = Khi·Ehiᵀ
#pragma unroll
        for (int which = 0; which < 2; which++) {
            float Ta[8][4];
#pragma unroll
            for (int i = 0; i < 8; i++)
#pragma unroll
                for (int q = 0; q < 4; q++) Ta[i][q] = 0.f;
#pragma unroll
            for (int ks = 0; ks < 4; ks++) {
                uint32_t ah[4];
                LDA(ah, which == 0 ? O_QHI : O_KHI, sm0, ks);
#pragma unroll
                for (int p = 0; p < 4; p++) {
                    uint32_t be[4];
                    LDB(be, O_ES, en0 + 16 * p, ks);
                    mma_bf16(Ta[p * 2 + 0], ah, be[0], be[1]);
                    mma_bf16(Ta[p * 2 + 1], ah, be[2], be[3]);
                }
            }
            const int obase = which == 0 ? O_T1 : O_T2;
            int row = sm0 + (lane >> 2);
#pragma unroll
            for (int i = 0; i < 8; i++) {
                int col = en0 + 16 * (i >> 1) + 8 * (i & 1) + 2 * (lane & 3);
                *(uint32_t*)(smem + obase + row * 256 + col * 2) =
                    bf2u32(Ta[i][0], Ta[i][1]);
                *(uint32_t*)(smem + obase + (row + 8) * 256 + col * 2) =
                    bf2u32(Ta[i][2], Ta[i][3]);
            }
        }
        __syncthreads();   // B3: all warps done reading E -> sS may overwrite

        // write S fp32 (overlay on E region), stride 66
        {
            float* sS = (float*)(smem + O_ES);
            int row = sm0 + (lane >> 2);
            int col0 = sn0 + 2 * (lane & 3);
#pragma unroll
            for (int nt = 0; nt < 4; nt++) {
                int col = col0 + nt * 8;
                *(float2*)(sS + row * 66 + col) =
                    make_float2(Sa[nt][0], Sa[nt][1]);
                *(float2*)(sS + (row + 8) * 66 + col) =
                    make_float2(Sa[nt][2], Sa[nt][3]);
            }
        }
        __syncthreads();   // B4

        // ---- softmax with diagonal gather (thread (lp, j) owns 16 r's)
        float pv[16];
        {
            const float* sS = (const float*)(smem + O_ES);
            const __nv_bfloat16* T1 = (const __nv_bfloat16*)(smem + O_T1);
            const __nv_bfloat16* T2 = (const __nv_bfloat16*)(smem + O_T2);
            const float* sM = (const float*)(smem + O_M);
            float sv[16];
            float mt = -1e30f;
#pragma unroll
            for (int q = 0; q < 16; q++) {
                int r = 16 * j + q;
                int w = lp - r + 63;
                float s = (sS[lp * 66 + r]
                           + __bfloat162float(T1[lp * 128 + w])
                           + __bfloat162float(T2[r * 128 + w])) * 0.125f
                          + sM[r];
                sv[q] = s;
                mt = fmaxf(mt, s);
            }
            mt = fmaxf(mt, __shfl_xor_sync(0xffffffffu, mt, 1));
            mt = fmaxf(mt, __shfl_xor_sync(0xffffffffu, mt, 2));
            float mnew = fmaxf(mrun, mt);
            float corr = __expf(mrun - mnew);
            float ps = 0.f;
#pragma unroll
            for (int q = 0; q < 16; q++) {
                pv[q] = __expf(sv[q] - mnew);
                ps += pv[q];
            }
            ps += __shfl_xor_sync(0xffffffffu, ps, 1);
            ps += __shfl_xor_sync(0xffffffffu, ps, 2);
            lsum = lsum * corr + ps;
            mrun = mnew;
            if ((tid & 3) == 0) ((float*)(smem + O_C))[lp] = corr;
        }
        __syncthreads();   // B5: T1/T2 reads done -> P may overlay

        // write P hi/lo bf16 (rows lp, 128B rows, swizzled), overlay T1/T2
        {
            ushort ph[16], pl[16];
#pragma unroll
            for (int q = 0; q < 16; q++) {
                __nv_bfloat16 h = __float2bfloat16(pv[q]);
                float rest = pv[q] - __bfloat162float(h);
                ph[q] = __bfloat16_as_ushort(h);
                pl[q] = __bfloat16_as_ushort(__float2bfloat16(rest));
            }
#pragma unroll
            for (int cc = 0; cc < 2; cc++) {
                uint4 uh, ul;
                const ushort* hp = ph + cc * 8;
                const ushort* lpt = pl + cc * 8;
                uh.x = (uint32_t)hp[0] | ((uint32_t)hp[1] << 16);
                uh.y = (uint32_t)hp[2] | ((uint32_t)hp[3] << 16);
                uh.z = (uint32_t)hp[4] | ((uint32_t)hp[5] << 16);
                uh.w = (uint32_t)hp[6] | ((uint32_t)hp[7] << 16);
                ul.x = (uint32_t)lpt[0] | ((uint32_t)lpt[1] << 16);
                ul.y = (uint32_t)lpt[2] | ((uint32_t)lpt[3] << 16);
                ul.z = (uint32_t)lpt[4] | ((uint32_t)lpt[5] << 16);
                ul.w = (uint32_t)lpt[6] | ((uint32_t)lpt[7] << 16);
                int off = SWB(lp, 2 * j + cc);
                *(uint4*)(smem + O_T1 + off) = uh;
                *(uint4*)(smem + O_T2 + off) = ul;
            }
        }
        __syncthreads();   // B6

        // ---- PV: O = corr*O + P·V (3 products), V via ldmatrix.trans
        {
            const float* sC = (const float*)(smem + O_C);
            float cA = sC[sm0 + (lane >> 2)];
            float cB = sC[sm0 + 8 + (lane >> 2)];
#pragma unroll
            for (int nt = 0; nt < 4; nt++) {
                Oa[nt][0] *= cA; Oa[nt][1] *= cA;
                Oa[nt][2] *= cB; Oa[nt][3] *= cB;
            }
#pragma unroll
            for (int ks = 0; ks < 4; ks++) {
                uint32_t ph_[4], pl_[4];
                LDA(ph_, O_T1, sm0, ks);
                LDA(pl_, O_T2, sm0, ks);
                uint32_t vh0[4], vh1[4], vl0[4], vl1[4];
                LDBT(vh0, O_VHI, 16 * ks, sn0);
                LDBT(vh1, O_VHI, 16 * ks, sn0 + 16);
                LDBT(vl0, O_VLO, 16 * ks, sn0);
                LDBT(vl1, O_VLO, 16 * ks, sn0 + 16);
#pragma unroll
                for (int nt = 0; nt < 4; nt++) {
                    uint32_t* vh = (nt < 2) ? vh0 : vh1;
                    uint32_t* vl = (nt < 2) ? vl0 : vl1;
                    int s2 = (nt & 1) * 2;
                    mma_bf16(Oa[nt], ph_, vh[s2], vh[s2 + 1]);
                    mma_bf16(Oa[nt], pl_, vh[s2], vh[s2 + 1]);
                    mma_bf16(Oa[nt], ph_, vl[s2], vl[s2 + 1]);
                }
            }
        }
    }

    __syncthreads();
    if ((tid & 3) == 0) ((float*)(smem + O_L))[lp] = 1.f / lsum;
    __syncthreads();
    const float* sL = (const float*)(smem + O_L);
    float iA = sL[sm0 + (lane >> 2)];
    float iB = sL[sm0 + 8 + (lane >> 2)];
#pragma unroll
    for (int nt = 0; nt < 4; nt++) {
        int row = l0 + sm0 + (lane >> 2);
        int col = head * 64 + sn0 + nt * 8 + 2 * (lane & 3);
        float* op = out + ((size_t)(b * SEQ + row)) * HID + col;
        *(float2*)op = make_float2(Oa[nt][0] * iA, Oa[nt][1] * iA);
        *(float2*)(op + 8 * HID) = make_float2(Oa[nt][2] * iB, Oa[nt][3] * iB);
    }
}

// ---------------------------------------------------------------------------
extern "C" void kernel_launch(void* const* d_in, const int* in_sizes, int n_in,
                              void* d_out, int out_size) {
    const float* X    = (const float*)d_in[0];
    const float* W    = (const float*)d_in[1];
    const float* bias = (const float*)d_in[2];
    const float* E    = (const float*)d_in[3];
    const float* msk  = (const float*)d_in[4];
    float* out = (float*)d_out;

    const size_t NV = ((size_t)BB * SEQ * HID + (size_t)3 * HID * HID
                       + (size_t)EROWS * HD) / 4;
    split_kernel<<<(unsigned)((NV + 255) / 256), 256>>>(X, W, E);

    cudaFuncSetAttribute(qkv_mma_kernel,
                         cudaFuncAttributeMaxDynamicSharedMemorySize, QKV_SMEM);
    dim3 g1(3 * HID / GN, (BB * SEQ) / GM);
    qkv_mma_kernel<<<g1, 256, QKV_SMEM>>>(bias);

    cudaFuncSetAttribute(attn_mma_kernel,
                         cudaFuncAttributeMaxDynamicSharedMemorySize, ATT_SMEM);
    dim3 g2(SEQ / 64, BH);
    attn_mma_kernel<<<g2, 256, ATT_SMEM>>>(msk, out);
}

// round 13
// speedup vs baseline: 4.0228x; 1.3240x over previous
#include <cuda_runtime.h>
#include <cuda_bf16.h>
#include <cstdint>
#include <cstddef>

typedef unsigned long long u64;

// Problem constants
constexpr int SEQ  = 1024;
constexpr int HID  = 1024;
constexpr int NH   = 16;
constexpr int HD   = 64;
constexpr int BB   = 4;
constexpr int BH   = BB * NH;      // 64
constexpr int EROWS = 2 * 1024 - 1; // 2047

// bf16 hi/lo splits (inputs + intermediates), head-major Q/K/V
__device__ __align__(16) __nv_bfloat16 g_Xhi[(size_t)BB * SEQ * HID];
__device__ __align__(16) __nv_bfloat16 g_Xlo[(size_t)BB * SEQ * HID];
__device__ __align__(16) __nv_bfloat16 g_Whi[(size_t)3 * HID * HID];
__device__ __align__(16) __nv_bfloat16 g_Wlo[(size_t)3 * HID * HID];
__device__ __align__(16) __nv_bfloat16 g_Ehi[(size_t)EROWS * HD];
__device__ __align__(16) __nv_bfloat16 g_Qhi[(size_t)BH * SEQ * HD];
__device__ __align__(16) __nv_bfloat16 g_Qlo[(size_t)BH * SEQ * HD];
__device__ __align__(16) __nv_bfloat16 g_Khi[(size_t)BH * SEQ * HD];
__device__ __align__(16) __nv_bfloat16 g_Klo[(size_t)BH * SEQ * HD];
__device__ __align__(16) __nv_bfloat16 g_Vhi[(size_t)BH * SEQ * HD];
__device__ __align__(16) __nv_bfloat16 g_Vlo[(size_t)BH * SEQ * HD];

// ---------------------------------------------------------------------------
// helpers
// ---------------------------------------------------------------------------
__device__ __forceinline__ uint32_t smem_u32(const void* p) {
    uint32_t a;
    asm("{ .reg .u64 t; cvta.to.shared.u64 t, %1; cvt.u32.u64 %0, t; }"
        : "=r"(a) : "l"(p));
    return a;
}
__device__ __forceinline__ void ldsm4(uint32_t* r, uint32_t addr) {
    asm volatile("ldmatrix.sync.aligned.m8n8.x4.shared.b16 {%0,%1,%2,%3}, [%4];"
                 : "=r"(r[0]), "=r"(r[1]), "=r"(r[2]), "=r"(r[3]) : "r"(addr));
}
__device__ __forceinline__ void ldsm4t(uint32_t* r, uint32_t addr) {
    asm volatile("ldmatrix.sync.aligned.m8n8.x4.trans.shared.b16 {%0,%1,%2,%3}, [%4];"
                 : "=r"(r[0]), "=r"(r[1]), "=r"(r[2]), "=r"(r[3]) : "r"(addr));
}
__device__ __forceinline__ void mma_bf16(float* c, const uint32_t* a,
                                         uint32_t b0, uint32_t b1) {
    asm volatile(
        "mma.sync.aligned.m16n8k16.row.col.f32.bf16.bf16.f32 "
        "{%0,%1,%2,%3}, {%4,%5,%6,%7}, {%8,%9}, {%0,%1,%2,%3};"
        : "+f"(c[0]), "+f"(c[1]), "+f"(c[2]), "+f"(c[3])
        : "r"(a[0]), "r"(a[1]), "r"(a[2]), "r"(a[3]), "r"(b0), "r"(b1));
}
__device__ __forceinline__ void cp16(uint32_t dst, const void* src) {
    asm volatile("cp.async.cg.shared.global [%0], [%1], 16;" :: "r"(dst), "l"(src));
}
__device__ __forceinline__ int SWB(int r, int c) {
    return r * 128 + (((c ^ (r & 7))) << 4);
}
__device__ __forceinline__ float ex2f(float x) {
    float y;
    asm("ex2.approx.f32 %0, %1;" : "=f"(y) : "f"(x));
    return y;
}
__device__ __forceinline__ float bflo(uint32_t v) {
    return __bfloat162float(__ushort_as_bfloat16((ushort)(v & 0xFFFF)));
}
__device__ __forceinline__ float bfhi(uint32_t v) {
    return __bfloat162float(__ushort_as_bfloat16((ushort)(v >> 16)));
}

// ---------------------------------------------------------------------------
// Kernel 0: split X, W into bf16 hi/lo; E -> bf16
// ---------------------------------------------------------------------------
__global__ __launch_bounds__(256)
void split_kernel(const float* __restrict__ X, const float* __restrict__ W,
                  const float* __restrict__ E) {
    const size_t NX = (size_t)BB * SEQ * HID / 4;
    const size_t NW = (size_t)3 * HID * HID / 4;
    const size_t NE = (size_t)EROWS * HD / 4;
    size_t i = (size_t)blockIdx.x * 256 + threadIdx.x;
    if (i < NX + NW) {
        const float4* src;
        __nv_bfloat16 *hi, *lo;
        size_t off;
        if (i < NX) { src = (const float4*)X; hi = g_Xhi; lo = g_Xlo; off = i; }
        else        { src = (const float4*)W; hi = g_Whi; lo = g_Wlo; off = i - NX; }
        float4 v = src[off];
        float vv[4] = {v.x, v.y, v.z, v.w};
        ushort h[4], l[4];
#pragma unroll
        for (int q = 0; q < 4; q++) {
            __nv_bfloat16 hb = __float2bfloat16(vv[q]);
            __nv_bfloat16 lb = __float2bfloat16(vv[q] - __bfloat162float(hb));
            h[q] = __bfloat16_as_ushort(hb);
            l[q] = __bfloat16_as_ushort(lb);
        }
        uint2 hp, lp;
        hp.x = (uint32_t)h[0] | ((uint32_t)h[1] << 16);
        hp.y = (uint32_t)h[2] | ((uint32_t)h[3] << 16);
        lp.x = (uint32_t)l[0] | ((uint32_t)l[1] << 16);
        lp.y = (uint32_t)l[2] | ((uint32_t)l[3] << 16);
        ((uint2*)hi)[off] = hp;
        ((uint2*)lo)[off] = lp;
    } else if (i < NX + NW + NE) {
        size_t off = i - NX - NW;
        float4 v = ((const float4*)E)[off];
        uint2 hp;
        hp.x = (uint32_t)__bfloat16_as_ushort(__float2bfloat16(v.x))
             | ((uint32_t)__bfloat16_as_ushort(__float2bfloat16(v.y)) << 16);
        hp.y = (uint32_t)__bfloat16_as_ushort(__float2bfloat16(v.z))
             | ((uint32_t)__bfloat16_as_ushort(__float2bfloat16(v.w)) << 16);
        ((uint2*)g_Ehi)[off] = hp;
    }
}

// ---------------------------------------------------------------------------
// Kernel 1: QKV via mma.sync bf16x3 -> bf16 hi/lo head-major (validated R9)
// ---------------------------------------------------------------------------
constexpr int GM = 128;
constexpr int GN = 128;
constexpr int GK = 64;
constexpr int NKT = HID / GK;
constexpr int ARR_B  = GM * GK * 2;
constexpr int STAGE  = 4 * ARR_B;
constexpr int QKV_SMEM = 2 * STAGE;

__global__ __launch_bounds__(256, 1)
void qkv_mma_kernel(const float* __restrict__ bias) {
    extern __shared__ char smem[];
    const uint32_t sbase = smem_u32(smem);
    const int tid  = threadIdx.x;
    const int w    = tid >> 5;
    const int lane = tid & 31;
    const int wm   = w & 1;
    const int wn   = w >> 1;

    const int n0 = blockIdx.x * GN;
    const int m0 = blockIdx.y * GM;

    auto load_stage = [&](int stg, int kt) {
        const int k0 = kt * GK;
        const uint32_t sb = sbase + stg * STAGE;
#pragma unroll
        for (int p = 0; p < 4; p++) {
            int ci = tid + p * 256;
            int r = ci >> 3, c = ci & 7;
            uint32_t off = (uint32_t)(r * 128 + ((c ^ (r & 7)) * 16));
            size_t goA = (size_t)(m0 + r) * HID + k0 + c * 8;
            size_t goB = (size_t)(n0 + r) * HID + k0 + c * 8;
            cp16(sb + off,              g_Xhi + goA);
            cp16(sb + ARR_B + off,      g_Xlo + goA);
            cp16(sb + 2 * ARR_B + off,  g_Whi + goB);
            cp16(sb + 3 * ARR_B + off,  g_Wlo + goB);
        }
        asm volatile("cp.async.commit_group;");
    };

    float acc[4][4][4];
#pragma unroll
    for (int mt = 0; mt < 4; mt++)
#pragma unroll
        for (int nt = 0; nt < 4; nt++)
#pragma unroll
            for (int q = 0; q < 4; q++) acc[mt][nt][q] = 0.f;

    load_stage(0, 0);

    for (int kt = 0; kt < NKT; kt++) {
        const bool has_next = (kt + 1 < NKT);
        if (has_next) load_stage((kt + 1) & 1, kt + 1);
        if (has_next) asm volatile("cp.async.wait_group 1;");
        else          asm volatile("cp.async.wait_group 0;");
        __syncthreads();

        const uint32_t sAhi = sbase + (kt & 1) * STAGE;
        const uint32_t sAlo = sAhi + ARR_B;
        const uint32_t sBhi = sAhi + 2 * ARR_B;
        const uint32_t sBlo = sAhi + 3 * ARR_B;

#pragma unroll
        for (int ks = 0; ks < 4; ks++) {
            uint32_t bhi[2][4], blo[2][4];
#pragma unroll
            for (int p2 = 0; p2 < 2; p2++) {
                int row = wn * 32 + p2 * 16 + (lane & 7) + ((lane >> 4) & 1) * 8;
                int c   = ks * 2 + ((lane >> 3) & 1);
                uint32_t off = (uint32_t)(row * 128 + ((c ^ (row & 7)) * 16));
                ldsm4(bhi[p2], sBhi + off);
                ldsm4(blo[p2], sBlo + off);
            }
#pragma unroll
            for (int mt = 0; mt < 4; mt++) {
                int row = wm * 64 + mt * 16 + (lane & 15);
                int c   = ks * 2 + (lane >> 4);
                uint32_t off = (uint32_t)(row * 128 + ((c ^ (row & 7)) * 16));
                uint32_t ahi[4], alo[4];
                ldsm4(ahi, sAhi + off);
                ldsm4(alo, sAlo + off);
#pragma unroll
                for (int nt = 0; nt < 4; nt++) {
                    int pr = nt >> 1, sub = nt & 1;
                    uint32_t b0h = bhi[pr][sub * 2], b1h = bhi[pr][sub * 2 + 1];
                    uint32_t b0l = blo[pr][sub * 2], b1l = blo[pr][sub * 2 + 1];
                    mma_bf16(acc[mt][nt], ahi, b0h, b1h);
                    mma_bf16(acc[mt][nt], ahi, b0l, b1l);
                    mma_bf16(acc[mt][nt], alo, b0h, b1h);
                }
            }
        }
        __syncthreads();
    }

#pragma unroll
    for (int nt = 0; nt < 4; nt++) {
        const int col0 = n0 + wn * 32 + nt * 8 + (lane & 3) * 2;
        const int part = col0 >> 10;
        const int rem  = col0 & 1023;
        const int head = rem >> 6;
        const int d    = rem & 63;
        __nv_bfloat16* dhi = (part == 0) ? g_Qhi : (part == 1) ? g_Khi : g_Vhi;
        __nv_bfloat16* dlo = (part == 0) ? g_Qlo : (part == 1) ? g_Klo : g_Vlo;
        float2 b2 = *(const float2*)(bias + col0);
#pragma unroll
        for (int mt = 0; mt < 4; mt++) {
            int row0 = m0 + wm * 64 + mt * 16 + (lane >> 2);
#pragma unroll
            for (int h = 0; h < 2; h++) {
                int row = row0 + h * 8;
                int bq = row >> 10, s = row & 1023;
                float ox = acc[mt][nt][h * 2 + 0] + b2.x;
                float oy = acc[mt][nt][h * 2 + 1] + b2.y;
                __nv_bfloat16 hx = __float2bfloat16(ox);
                __nv_bfloat16 hy = __float2bfloat16(oy);
                float lx = ox - __bfloat162float(hx);
                float ly = oy - __bfloat162float(hy);
                size_t idx = ((size_t)(bq * NH + head) * SEQ + s) * HD + d;
                *(uint32_t*)(dhi + idx) =
                    (uint32_t)__bfloat16_as_ushort(hx)
                  | ((uint32_t)__bfloat16_as_ushort(hy) << 16);
                *(uint32_t*)(dlo + idx) =
                    (uint32_t)__bfloat16_as_ushort(__float2bfloat16(lx))
                  | ((uint32_t)__bfloat16_as_ushort(__float2bfloat16(ly)) << 16);
            }
        }
    }
}

// ---------------------------------------------------------------------------
// Kernel 2: tensorized attention with diagonal-stored positional terms.
// ---------------------------------------------------------------------------
constexpr int O_QHI = 0;
constexpr int O_QLO = 8192;
constexpr int O_KHI = 16384;
constexpr int O_KLO = 24576;
constexpr int O_VHI = 32768;
constexpr int O_VLO = 40960;
constexpr int O_G1  = 49152;   // 64 x 136B  (bf16, row stride 136)
constexpr int O_G2  = 57856;   // 64 x 136B -> 66560
constexpr int O_EP  = 66560;   // E (swb, 127x128B) then P_hi(8K)+P_lo(8K)
constexpr int O_S   = 82944;   // 64 x 68 fp32 (chunk-XOR swizzled)
constexpr int O_M   = 100352;  // mask*log2e (64 fl)
constexpr int O_C   = 100608;  // corr
constexpr int O_L   = 100864;  // 1/lsum
constexpr int ATT_SMEM = 101120;

constexpr float CSC = 0.125f * 1.44269504f;   // (1/8)*log2(e)
constexpr float L2E = 1.44269504f;

__global__ __launch_bounds__(256, 2)
void attn_mma_kernel(const float* __restrict__ mask, float* __restrict__ out) {
    extern __shared__ char smem[];
    const uint32_t sb = smem_u32(smem);
    const int tid  = threadIdx.x;
    const int wid  = tid >> 5;
    const int lane = tid & 31;
    const int bh   = blockIdx.y;
    const int b    = bh >> 4;
    const int head = bh & 15;
    const int l0   = blockIdx.x * 64;
    const int sm0  = 16 * (wid & 3);
    const int half = wid >> 2;                 // 0/1: which w-tile subset
    const int sn0  = 32 * half;
    const int q4   = sm0 >> 4;
    const int lp   = tid >> 2;
    const int j    = tid & 3;
    const size_t hb = (size_t)bh * SEQ * HD;

    auto LDA = [&](uint32_t* f, int obase, int m0_, int ks) {
        int row = m0_ + (lane & 15);
        int c   = ks * 2 + (lane >> 4);
        ldsm4(f, sb + obase + SWB(row, c));
    };
    auto LDB = [&](uint32_t* f, int obase, int n0_, int ks) {
        int row = n0_ + (lane & 7) + (((lane >> 4) & 1) << 3);
        int c   = ks * 2 + ((lane >> 3) & 1);
        ldsm4(f, sb + obase + SWB(row, c));
    };
    auto LDBT = [&](uint32_t* f, int obase, int k0, int ncol) {
        int row = k0 + (lane & 7) + (((lane >> 3) & 1) << 3);
        int c   = (ncol >> 3) + ((lane >> 4) & 1);
        ldsm4t(f, sb + obase + SWB(row, c));
    };

    // load Q hi/lo tiles once
#pragma unroll
    for (int p = 0; p < 4; p++) {
        int ci = tid + p * 256;
        int m = ci >> 9, cj = ci & 511, r = cj >> 3, c = cj & 7;
        const __nv_bfloat16* src = ((m == 0) ? g_Qhi : g_Qlo)
                                   + hb + (size_t)(l0 + r) * HD + c * 8;
        *(uint4*)(smem + O_QHI + m * 8192 + SWB(r, c)) = *(const uint4*)src;
    }

    float Oa[4][4];
#pragma unroll
    for (int nt = 0; nt < 4; nt++)
#pragma unroll
        for (int q = 0; q < 4; q++) Oa[nt][q] = 0.f;
    float mrun = -30000.f, lsum = 0.f;

    for (int t = 0; t < 16; t++) {
        const int r0 = t * 64;
        __syncthreads();   // B1: prev PV done with P(E region)/V; K/V/E refill safe

        // async-load K/V hi/lo + E window
#pragma unroll
        for (int p = 0; p < 8; p++) {
            int ci = tid + p * 256;
            int m = ci >> 9, cj = ci & 511, r = cj >> 3, c = cj & 7;
            const __nv_bfloat16* base =
                (m == 0) ? g_Khi : (m == 1) ? g_Klo : (m == 2) ? g_Vhi : g_Vlo;
            cp16(sb + O_KHI + m * 8192 + SWB(r, c),
                 base + hb + (size_t)(r0 + r) * HD + c * 8);
        }
        const int ebase = l0 - r0 + 960;
        for (int idx = tid; idx < 127 * 8; idx += 256) {
            int ww = idx >> 3, c = idx & 7;
            cp16(sb + O_EP + SWB(ww, c),
                 g_Ehi + (size_t)(ebase + ww) * HD + c * 8);
        }
        if (tid < 64)
            ((float*)(smem + O_M))[tid] = mask[b * SEQ + r0 + tid] * L2E;
        asm volatile("cp.async.commit_group;");
        asm volatile("cp.async.wait_group 0;");
        __syncthreads();   // B2: tiles visible

        // ---- S = Q·Kᵀ (3 products)
        float Sa[4][4];
#pragma unroll
        for (int nt = 0; nt < 4; nt++)
#pragma unroll
            for (int q = 0; q < 4; q++) Sa[nt][q] = 0.f;
#pragma unroll
        for (int ks = 0; ks < 4; ks++) {
            uint32_t ahi[4], alo[4], b0h[4], b1h[4], b0l[4], b1l[4];
            LDA(ahi, O_QHI, sm0, ks); LDA(alo, O_QLO, sm0, ks);
            LDB(b0h, O_KHI, sn0, ks); LDB(b1h, O_KHI, sn0 + 16, ks);
            LDB(b0l, O_KLO, sn0, ks); LDB(b1l, O_KLO, sn0 + 16, ks);
#pragma unroll
            for (int nt = 0; nt < 4; nt++) {
                uint32_t* bh_ = (nt < 2) ? b0h : b1h;
                uint32_t* bl_ = (nt < 2) ? b0l : b1l;
                int s2 = (nt & 1) * 2;
                mma_bf16(Sa[nt], ahi, bh_[s2], bh_[s2 + 1]);
                mma_bf16(Sa[nt], ahi, bl_[s2], bl_[s2 + 1]);
                mma_bf16(Sa[nt], alo, bh_[s2], bh_[s2 + 1]);
            }
        }
        // S store (own region, chunk-XOR swizzle, stride 68 fl)
        {
            float* sS = (float*)(smem + O_S);
            int row = sm0 + (lane >> 2);
#pragma unroll
            for (int nt = 0; nt < 4; nt++) {
                int col = sn0 + nt * 8 + 2 * (lane & 3);
                int ch0 = (col >> 2) ^ (row & 3);
                int ch1 = (col >> 2) ^ ((row + 8) & 3);
                *(float2*)(sS + row * 68 + 4 * ch0 + (col & 3)) =
                    make_float2(Sa[nt][0], Sa[nt][1]);
                *(float2*)(sS + (row + 8) * 68 + 4 * ch1 + (col & 3)) =
                    make_float2(Sa[nt][2], Sa[nt][3]);
            }
        }

        // ---- T1/T2: band-limited, diagonal-stored (5 n16-tiles per warp)
        {
            uint32_t aT[4][4];
            // T1: A = Q_hi rows sm0; warp handles tiles [t1s, t1s+t1n)
#pragma unroll
            for (int ks = 0; ks < 4; ks++) LDA(aT[ks], O_QHI, sm0, ks);
            int t1s = q4 + (half ? 3 : 0);
            int t1n = half ? 2 : 3;
            for (int ti = 0; ti < t1n; ti++) {
                int p = t1s + ti;
                float Ta[2][4];
#pragma unroll
                for (int u = 0; u < 2; u++)
#pragma unroll
                    for (int v = 0; v < 4; v++) Ta[u][v] = 0.f;
#pragma unroll
                for (int ks = 0; ks < 4; ks++) {
                    uint32_t be[4];
                    LDB(be, O_EP, 16 * p, ks);
                    mma_bf16(Ta[0], aT[ks], be[0], be[1]);
                    mma_bf16(Ta[1], aT[ks], be[2], be[3]);
                }
#pragma unroll
                for (int u = 0; u < 2; u++)
#pragma unroll
                    for (int v = 0; v < 4; v++) {
                        int w_ = 16 * p + 8 * u + 2 * (lane & 3) + (v & 1);
                        int l_ = sm0 + (lane >> 2) + ((v >> 1) << 3);
                        int r_ = l_ - w_ + 63;
                        if (r_ >= 0 && r_ < 64)
                            *(__nv_bfloat16*)(smem + O_G1 + l_ * 136 + 2 * r_) =
                                __float2bfloat16(Ta[u][v]);
                    }
            }
            // T2: A = K_hi rows sm0; tiles [t2s, t2s+t2n)
#pragma unroll
            for (int ks = 0; ks < 4; ks++) LDA(aT[ks], O_KHI, sm0, ks);
            int t2s = (3 - q4) + (half ? 2 : 0);
            int t2n = half ? 3 : 2;
            for (int ti = 0; ti < t2n; ti++) {
                int p = t2s + ti;
                float Ta[2][4];
#pragma unroll
                for (int u = 0; u < 2; u++)
#pragma unroll
                    for (int v = 0; v < 4; v++) Ta[u][v] = 0.f;
#pragma unroll
                for (int ks = 0; ks < 4; ks++) {
                    uint32_t be[4];
                    LDB(be, O_EP, 16 * p, ks);
                    mma_bf16(Ta[0], aT[ks], be[0], be[1]);
                    mma_bf16(Ta[1], aT[ks], be[2], be[3]);
                }
#pragma unroll
                for (int u = 0; u < 2; u++)
#pragma unroll
                    for (int v = 0; v < 4; v++) {
                        int w_ = 16 * p + 8 * u + 2 * (lane & 3) + (v & 1);
                        int r_ = sm0 + (lane >> 2) + ((v >> 1) << 3);
                        int l_ = w_ + r_ - 63;
                        if (l_ >= 0 && l_ < 64)
                            *(__nv_bfloat16*)(smem + O_G2 + l_ * 136 + 2 * r_) =
                                __float2bfloat16(Ta[u][v]);
                    }
            }
        }
        __syncthreads();   // B3: S + G1 + G2 visible; E reads done

        // ---- softmax (thread (lp, j) owns r in [16j, 16j+16))
        float pvv[16];
        {
            const float* sS = (const float*)(smem + O_S);
            const float* sM = (const float*)(smem + O_M);
            float sv[16];
            float mt = -30000.f;
#pragma unroll
            for (int k = 0; k < 4; k++) {
                float4 s4 = *(const float4*)(sS + lp * 68 + 4 * ((4 * j + k) ^ (lp & 3)));
                uint2 g1 = *(const uint2*)(smem + O_G1 + lp * 136 + 32 * j + 8 * k);
                uint2 g2 = *(const uint2*)(smem + O_G2 + lp * 136 + 32 * j + 8 * k);
                float4 m4 = *(const float4*)(sM + 16 * j + 4 * k);
                float a0 = (s4.x + bflo(g1.x) + bflo(g2.x)) * CSC + m4.x;
                float a1 = (s4.y + bfhi(g1.x) + bfhi(g2.x)) * CSC + m4.y;
                float a2 = (s4.z + bflo(g1.y) + bflo(g2.y)) * CSC + m4.z;
                float a3 = (s4.w + bfhi(g1.y) + bfhi(g2.y)) * CSC + m4.w;
                sv[4*k+0] = a0; sv[4*k+1] = a1; sv[4*k+2] = a2; sv[4*k+3] = a3;
                mt = fmaxf(mt, fmaxf(fmaxf(a0, a1), fmaxf(a2, a3)));
            }
            mt = fmaxf(mt, __shfl_xor_sync(0xffffffffu, mt, 1));
            mt = fmaxf(mt, __shfl_xor_sync(0xffffffffu, mt, 2));
            float mnew = fmaxf(mrun, mt);
            float corr = ex2f(mrun - mnew);
            float ps = 0.f;
#pragma unroll
            for (int q = 0; q < 16; q++) {
                pvv[q] = ex2f(sv[q] - mnew);
                ps += pvv[q];
            }
            ps += __shfl_xor_sync(0xffffffffu, ps, 1);
            ps += __shfl_xor_sync(0xffffffffu, ps, 2);
            lsum = lsum * corr + ps;
            mrun = mnew;
            if ((tid & 3) == 0) ((float*)(smem + O_C))[lp] = corr;
        }
        // P hi/lo store (overlay E region, SWB layout)
        {
            ushort ph[16], pl[16];
#pragma unroll
            for (int q = 0; q < 16; q++) {
                __nv_bfloat16 h = __float2bfloat16(pvv[q]);
                float rest = pvv[q] - __bfloat162float(h);
                ph[q] = __bfloat16_as_ushort(h);
                pl[q] = __bfloat16_as_ushort(__float2bfloat16(rest));
            }
#pragma unroll
            for (int cc = 0; cc < 2; cc++) {
                uint4 uh, ul;
                const ushort* hp = ph + cc * 8;
                const ushort* lpt = pl + cc * 8;
                uh.x = (uint32_t)hp[0] | ((uint32_t)hp[1] << 16);
                uh.y = (uint32_t)hp[2] | ((uint32_t)hp[3] << 16);
                uh.z = (uint32_t)hp[4] | ((uint32_t)hp[5] << 16);
                uh.w = (uint32_t)hp[6] | ((uint32_t)hp[7] << 16);
                ul.x = (uint32_t)lpt[0] | ((uint32_t)lpt[1] << 16);
                ul.y = (uint32_t)lpt[2] | ((uint32_t)lpt[3] << 16);
                ul.z = (uint32_t)lpt[4] | ((uint32_t)lpt[5] << 16);
                ul.w = (uint32_t)lpt[6] | ((uint32_t)lpt[7] << 16);
                int off = SWB(lp, 2 * j + cc);
                *(uint4*)(smem + O_EP + off) = uh;
                *(uint4*)(smem + O_EP + 8192 + off) = ul;
            }
        }
        __syncthreads();   // B4: P + corr visible

        // ---- PV: O = corr*O + P·V (3 products)
        {
            const float* sC = (const float*)(smem + O_C);
            float cA = sC[sm0 + (lane >> 2)];
            float cB = sC[sm0 + 8 + (lane >> 2)];
#pragma unroll
            for (int nt = 0; nt < 4; nt++) {
                Oa[nt][0] *= cA; Oa[nt][1] *= cA;
                Oa[nt][2] *= cB; Oa[nt][3] *= cB;
            }
#pragma unroll
            for (int ks = 0; ks < 4; ks++) {
                uint32_t ph_[4], pl_[4];
                LDA(ph_, O_EP, sm0, ks);
                LDA(pl_, O_EP + 8192, sm0, ks);
                uint32_t vh0[4], vh1[4], vl0[4], vl1[4];
                LDBT(vh0, O_VHI, 16 * ks, sn0);
                LDBT(vh1, O_VHI, 16 * ks, sn0 + 16);
                LDBT(vl0, O_VLO, 16 * ks, sn0);
                LDBT(vl1, O_VLO, 16 * ks, sn0 + 16);
#pragma unroll
                for (int nt = 0; nt < 4; nt++) {
                    uint32_t* vh = (nt < 2) ? vh0 : vh1;
                    uint32_t* vl = (nt < 2) ? vl0 : vl1;
                    int s2 = (nt & 1) * 2;
                    mma_bf16(Oa[nt], ph_, vh[s2], vh[s2 + 1]);
                    mma_bf16(Oa[nt], pl_, vh[s2], vh[s2 + 1]);
                    mma_bf16(Oa[nt], ph_, vl[s2], vl[s2 + 1]);
                }
            }
        }
    }

    __syncthreads();
    if ((tid & 3) == 0) ((float*)(smem + O_L))[lp] = 1.f / lsum;
    __syncthreads();
    const float* sL = (const float*)(smem + O_L);
    float iA = sL[sm0 + (lane >> 2)];
    float iB = sL[sm0 + 8 + (lane >> 2)];
#pragma unroll
    for (int nt = 0; nt < 4; nt++) {
        int row = l0 + sm0 + (lane >> 2);
        int col = head * 64 + sn0 + nt * 8 + 2 * (lane & 3);
        float* op = out + ((size_t)(b * SEQ + row)) * HID + col;
        *(float2*)op = make_float2(Oa[nt][0] * iA, Oa[nt][1] * iA);
        *(float2*)(op + 8 * HID) = make_float2(Oa[nt][2] * iB, Oa[nt][3] * iB);
    }
}

// ---------------------------------------------------------------------------
extern "C" void kernel_launch(void* const* d_in, const int* in_sizes, int n_in,
                              void* d_out, int out_size) {
    const float* X    = (const float*)d_in[0];
    const float* W    = (const float*)d_in[1];
    const float* bias = (const float*)d_in[2];
    const float* E    = (const float*)d_in[3];
    const float* msk  = (const float*)d_in[4];
    float* out = (float*)d_out;

    const size_t NV = ((size_t)BB * SEQ * HID + (size_t)3 * HID * HID
                       + (size_t)EROWS * HD) / 4;
    split_kernel<<<(unsigned)((NV + 255) / 256), 256>>>(X, W, E);

    cudaFuncSetAttribute(qkv_mma_kernel,
                         cudaFuncAttributeMaxDynamicSharedMemorySize, QKV_SMEM);
    dim3 g1(3 * HID / GN, (BB * SEQ) / GM);
    qkv_mma_kernel<<<g1, 256, QKV_SMEM>>>(bias);

    cudaFuncSetAttribute(attn_mma_kernel,
                         cudaFuncAttributeMaxDynamicSharedMemorySize, ATT_SMEM);
    dim3 g2(SEQ / 64, BH);
    attn_mma_kernel<<<g2, 256, ATT_SMEM>>>(msk, out);
}